// round 14
// baseline (speedup 1.0000x reference)
#include <cuda_runtime.h>
#include <cuda_bf16.h>
#include <cuda_fp16.h>
#include <stdint.h>

#define BATCH 2
#define LSEQ  4096
#define HID   1024
#define DIM   64
#define NTOK  (BATCH * LSEQ)
#define LOG2GAMMA (-0.04580368961f)   /* log2(0.96875) */

// ---------------------------------------------------------------------------
// Device globals
// ---------------------------------------------------------------------------
__device__ __nv_bfloat16 g_Qh[NTOK * DIM];
__device__ __nv_bfloat16 g_Ql[NTOK * DIM];
__device__ __nv_bfloat16 g_Kh[NTOK * DIM];
__device__ __nv_bfloat16 g_Kl[NTOK * DIM];
__device__ __nv_bfloat16 g_Vth[NTOK * DIM];       // per-64-tile transposed [t][d][tok]
__device__ __nv_bfloat16 g_Vtl[NTOK * DIM];
__device__ __half g_Whf[192 * HID];               // W^T concat [Q|K|V], fp16
__device__ float4 g_CO[LSEQ * 32];                // xPos coefs (cq,sq,ck,sk)

// ---------------------------------------------------------------------------
// Tensor-core helpers (sm_80+ portable)
// ---------------------------------------------------------------------------
__device__ __forceinline__ uint32_t smem_u32(const void* p) {
    uint32_t a;
    asm("{ .reg .u64 t; cvta.to.shared.u64 t, %1; cvt.u32.u64 %0, t; }"
        : "=r"(a) : "l"(p));
    return a;
}
__device__ __forceinline__ void ldsm4(uint32_t* r, uint32_t addr) {
    asm volatile("ldmatrix.sync.aligned.m8n8.x4.shared.b16 {%0,%1,%2,%3}, [%4];"
                 : "=r"(r[0]), "=r"(r[1]), "=r"(r[2]), "=r"(r[3]) : "r"(addr));
}
__device__ __forceinline__ void mma_bf16(float* d, const uint32_t* a,
                                         uint32_t b0, uint32_t b1) {
    asm volatile(
        "mma.sync.aligned.m16n8k16.row.col.f32.bf16.bf16.f32 "
        "{%0,%1,%2,%3},{%4,%5,%6,%7},{%8,%9},{%0,%1,%2,%3};"
        : "+f"(d[0]), "+f"(d[1]), "+f"(d[2]), "+f"(d[3])
        : "r"(a[0]), "r"(a[1]), "r"(a[2]), "r"(a[3]), "r"(b0), "r"(b1));
}
__device__ __forceinline__ void mma_f16(float* d, const uint32_t* a,
                                        uint32_t b0, uint32_t b1) {
    asm volatile(
        "mma.sync.aligned.m16n8k16.row.col.f32.f16.f16.f32 "
        "{%0,%1,%2,%3},{%4,%5,%6,%7},{%8,%9},{%0,%1,%2,%3};"
        : "+f"(d[0]), "+f"(d[1]), "+f"(d[2]), "+f"(d[3])
        : "r"(a[0]), "r"(a[1]), "r"(a[2]), "r"(a[3]), "r"(b0), "r"(b1));
}
__device__ __forceinline__ uint32_t pack2(__nv_bfloat16 a, __nv_bfloat16 b) {
    __nv_bfloat162 p = __halves2bfloat162(a, b);
    return *(uint32_t*)&p;
}
__device__ __forceinline__ uint32_t pack2h(__half a, __half b) {
    __half2 p = __halves2half2(a, b);
    return *(uint32_t*)&p;
}
__device__ __forceinline__ void cpasync16(uint32_t dst, const void* src) {
    asm volatile("cp.async.cg.shared.global [%0], [%1], 16;"
                 :: "r"(dst), "l"(src));
}
__device__ __forceinline__ void cp_commit() {
    asm volatile("cp.async.commit_group;" ::: "memory");
}
template <int N>
__device__ __forceinline__ void cp_wait() {
    asm volatile("cp.async.wait_group %0;" :: "n"(N) : "memory");
}
__device__ __forceinline__ void bar_sync(int id, int cnt) {
    asm volatile("bar.sync %0, %1;" :: "r"(id), "r"(cnt) : "memory");
}

// ---------------------------------------------------------------------------
// Merged prep kernel.
// ---------------------------------------------------------------------------
__global__ __launch_bounds__(256) void prep_all(
    const float* __restrict__ Wq, const float* __restrict__ Wk,
    const float* __restrict__ Wv)
{
    __shared__ float t[32][33];
    if (blockIdx.x < 192) {
        const int tx = threadIdx.x & 31, ty = threadIdx.x >> 5;
        const int k0 = (blockIdx.x & 31) * 32;
        const int n0 = (blockIdx.x >> 5) * 32;
        const float* W = (n0 < 64) ? Wq : ((n0 < 128) ? Wk : Wv);
        const int ncol = n0 & 63;
#pragma unroll
        for (int i = 0; i < 4; i++) {
            int k = k0 + ty + i * 8;
            t[ty + i * 8][tx] = W[k * DIM + ncol + tx];
        }
        __syncthreads();
#pragma unroll
        for (int i = 0; i < 4; i++) {
            int n = n0 + ty + i * 8;
            g_Whf[(size_t)n * HID + k0 + tx] = __float2half_rn(t[tx][ty + i * 8]);
        }
    } else {
        int idx = (blockIdx.x - 192) * 256 + threadIdx.x;
        int l = idx >> 5;
        int i = idx & 31;
        float fl = (float)l;
        float inv_freq = exp2f(-(float)i * (13.287712379549449f / 32.0f));
        float sn, cs;
        sincosf(fl * inv_freq, &sn, &cs);
        float sv = ((float)(2 * i) + 25.6f) / 89.6f;
        float scq = exp2f(fl * (log2f(sv) * (1.0f / 512.0f)));
        g_CO[idx] = make_float4(cs * scq, sn * scq, cs / scq, sn / scq);
    }
}

// ---------------------------------------------------------------------------
// QKV projection, 2-term fp16 (unchanged from R12).
// ---------------------------------------------------------------------------
#define XS    72
#define XBUF  (2 * 64 * XS * 2)
#define OXL   (64 * XS * 2)
#define OW    (2 * XBUF)
#define WBUF  (192 * XS * 2)
#define QKV_SMEM (OW + 2 * WBUF)                  /* 92160 */

__global__ __launch_bounds__(512, 1) void qkv_mma(const float* __restrict__ X)
{
    extern __shared__ char smem[];
    const uint32_t sb = smem_u32(smem);
    const int tid  = threadIdx.x;
    const int lane = tid & 31;
    const int wid  = tid >> 5;
    const int mr   = (wid >> 2) * 16;
    const int nc   = (wid & 3) * 48;
    const int row0 = blockIdx.x * 64;

    const int xr = tid >> 3;
    const int xc = (tid & 7) << 2;
    const int wn0 = tid >> 3;
    const int wc8 = (tid & 7) << 3;

    float acc[6][4];
#pragma unroll
    for (int b = 0; b < 6; b++)
#pragma unroll
        for (int c = 0; c < 4; c++) acc[b][c] = 0.f;

    {
#pragma unroll
        for (int it = 0; it < 3; it++) {
            int n = wn0 + it * 64;
            cpasync16(sb + OW + (uint32_t)(n * XS + wc8) * 2, &g_Whf[n * HID + wc8]);
        }
        cp_commit();
#pragma unroll
        for (int it = 0; it < 2; it++) {
            int c = xc + it * 32;
            float4 x = *(const float4*)&X[(size_t)(row0 + xr) * HID + c];
            __half hx = __float2half_rn(x.x);
            __half hy = __float2half_rn(x.y);
            __half hz = __float2half_rn(x.z);
            __half hw = __float2half_rn(x.w);
            uint32_t off = (uint32_t)(xr * XS + c) * 2;
            *(uint2*)(smem + off)       = make_uint2(pack2h(hx, hy), pack2h(hz, hw));
            *(uint2*)(smem + OXL + off) = make_uint2(
                pack2h(__float2half_rn(x.x - __half2float(hx)),
                       __float2half_rn(x.y - __half2float(hy))),
                pack2h(__float2half_rn(x.z - __half2float(hz)),
                       __float2half_rn(x.w - __half2float(hw))));
        }
    }

    for (int ch = 0; ch < 16; ch++) {
        const uint32_t xb = sb + (uint32_t)(ch & 1) * XBUF;
        const uint32_t wb = sb + OW + (uint32_t)(ch & 1) * WBUF;
        cp_wait<0>();
        __syncthreads();

        float4 xpre[2];
        if (ch < 15) {
            const int kcn = (ch + 1) * 64;
            uint32_t wbn = sb + OW + (uint32_t)((ch + 1) & 1) * WBUF;
#pragma unroll
            for (int it = 0; it < 3; it++) {
                int n = wn0 + it * 64;
                cpasync16(wbn + (uint32_t)(n * XS + wc8) * 2,
                          &g_Whf[n * HID + kcn + wc8]);
            }
            cp_commit();
#pragma unroll
            for (int it = 0; it < 2; it++)
                xpre[it] = *(const float4*)&X[(size_t)(row0 + xr) * HID + kcn + xc + it * 32];
        }

        const int lrow = lane & 15;
        const int lcg  = (lane >> 4) << 3;
#pragma unroll
        for (int ks = 0; ks < 4; ks++) {
            const int lcol = ks * 16 + lcg;
            uint32_t ah[4], al[4], bh[3][4];
            {
                uint32_t off = (uint32_t)((mr + lrow) * XS + lcol) * 2;
                ldsm4(ah, xb + off);
                ldsm4(al, xb + OXL + off);
            }
#pragma unroll
            for (int nf = 0; nf < 3; nf++) {
                uint32_t off = (uint32_t)((nc + nf * 16 + lrow) * XS + lcol) * 2;
                ldsm4(bh[nf], wb + off);
            }
#pragma unroll
            for (int nf = 0; nf < 3; nf++) {
                mma_f16(acc[nf * 2],     ah, bh[nf][0], bh[nf][2]);
                mma_f16(acc[nf * 2],     al, bh[nf][0], bh[nf][2]);
                mma_f16(acc[nf * 2 + 1], ah, bh[nf][1], bh[nf][3]);
                mma_f16(acc[nf * 2 + 1], al, bh[nf][1], bh[nf][3]);
            }
        }

        if (ch < 15) {
            char* xdn = smem + (size_t)((ch + 1) & 1) * XBUF;
#pragma unroll
            for (int it = 0; it < 2; it++) {
                int c = xc + it * 32;
                float4 x = xpre[it];
                __half hx = __float2half_rn(x.x);
                __half hy = __float2half_rn(x.y);
                __half hz = __float2half_rn(x.z);
                __half hw = __float2half_rn(x.w);
                uint32_t off = (uint32_t)(xr * XS + c) * 2;
                *(uint2*)(xdn + off)       = make_uint2(pack2h(hx, hy), pack2h(hz, hw));
                *(uint2*)(xdn + OXL + off) = make_uint2(
                    pack2h(__float2half_rn(x.x - __half2float(hx)),
                           __float2half_rn(x.y - __half2float(hy))),
                    pack2h(__float2half_rn(x.z - __half2float(hz)),
                           __float2half_rn(x.w - __half2float(hw))));
            }
        }
    }

    const int r4 = lane >> 2;
    const int c2 = (lane & 3) * 2;
#pragma unroll
    for (int h2 = 0; h2 < 2; h2++) {
        int g = row0 + mr + h2 * 8 + r4;
        int l = g & (LSEQ - 1);
#pragma unroll
        for (int nf = 0; nf < 6; nf++) {
            int col0 = nc + nf * 8;
            int mat  = col0 >> 6;
            int lcol = (col0 & 63) + c2;
            float v0 = acc[nf][h2 * 2 + 0];
            float v1 = acc[nf][h2 * 2 + 1];
            if (mat == 0) {
                float4 co = g_CO[l * 32 + (lcol >> 1)];
                float o0 = v0 * co.x - v1 * co.y;
                float o1 = v1 * co.x + v0 * co.y;
                __nv_bfloat16 h0 = __float2bfloat16(o0);
                __nv_bfloat16 h1 = __float2bfloat16(o1);
                *(uint32_t*)&g_Qh[g * DIM + lcol] = pack2(h0, h1);
                *(uint32_t*)&g_Ql[g * DIM + lcol] =
                    pack2(__float2bfloat16(o0 - __bfloat162float(h0)),
                          __float2bfloat16(o1 - __bfloat162float(h1)));
            } else if (mat == 1) {
                float4 co = g_CO[l * 32 + (lcol >> 1)];
                float o0 = v0 * co.z - v1 * co.w;
                float o1 = v1 * co.z + v0 * co.w;
                __nv_bfloat16 h0 = __float2bfloat16(o0);
                __nv_bfloat16 h1 = __float2bfloat16(o1);
                *(uint32_t*)&g_Kh[g * DIM + lcol] = pack2(h0, h1);
                *(uint32_t*)&g_Kl[g * DIM + lcol] =
                    pack2(__float2bfloat16(o0 - __bfloat162float(h0)),
                          __float2bfloat16(o1 - __bfloat162float(h1)));
            } else {
                int t = g >> 6, tok = g & 63;
                __nv_bfloat16 h0 = __float2bfloat16(v0);
                __nv_bfloat16 h1 = __float2bfloat16(v1);
                g_Vth[t * 4096 + lcol * 64 + tok]       = h0;
                g_Vth[t * 4096 + (lcol + 1) * 64 + tok] = h1;
                g_Vtl[t * 4096 + lcol * 64 + tok] =
                    __float2bfloat16(v0 - __bfloat162float(h0));
                g_Vtl[t * 4096 + (lcol + 1) * 64 + tok] =
                    __float2bfloat16(v1 - __bfloat162float(h1));
            }
        }
    }
}

// ---------------------------------------------------------------------------
// Fused banded decay attention: ONE 512-thread CTA per (b, qt).
// Warps 0-7  (ph=0): kt in [qt-3, qt]   — with diagonal mask at kt==qt
// Warps 8-15 (ph=1): kt in [qt-7, qt-4]
// Each half: private cp.async double-buffered KV pipeline + named barrier.
// Final 4-group (jc x ph) reduction in smem -> Out. No combine kernel.
// ---------------------------------------------------------------------------
#define AS     72
#define TILE_B (64 * AS * 2)               /* 9216 */
#define OQH_A  0
#define OQL_A  TILE_B
#define OKV    (2 * TILE_B)                /* 18432 */
#define KVBUF  (4 * TILE_B)                /* 36864: KH, KL, VH, VL */
#define PHSTR  (2 * KVBUF)                 /* 73728 per half */
#define OFF_KH 0
#define OFF_KL TILE_B
#define OFF_VH (2 * TILE_B)
#define OFF_VL (3 * TILE_B)
#define ATTN_SMEM (OKV + 2 * PHSTR)        /* 165888 */
#define RED_S  68
#define REDBUF (64 * RED_S * 4)            /* 17408 bytes per group */

__device__ __forceinline__ void attn_prefetch_kv(
    uint32_t kvb, int m0, int tile, int gtid)
{
#pragma unroll
    for (int it = 0; it < 2; it++) {
        int s = it * 256 + gtid;
        int r = s >> 3, c8 = (s & 7) << 3;
        uint32_t off = (uint32_t)(r * AS + c8) * 2;
        cpasync16(kvb + OFF_KH + off, &g_Kh[(size_t)(m0 + r) * DIM + c8]);
        cpasync16(kvb + OFF_KL + off, &g_Kl[(size_t)(m0 + r) * DIM + c8]);
        cpasync16(kvb + OFF_VH + off, &g_Vth[(size_t)tile * 4096 + r * 64 + c8]);
        cpasync16(kvb + OFF_VL + off, &g_Vtl[(size_t)tile * 4096 + r * 64 + c8]);
    }
    cp_commit();
}

__global__ __launch_bounds__(512, 1) void attn_mma(float* __restrict__ Out)
{
    extern __shared__ char sm[];
    const uint32_t sb = smem_u32(sm);
    const int tid  = threadIdx.x;
    const int lane = tid & 31;
    const int wid  = tid >> 5;          // 0..15
    const int ph   = wid >> 3;          // band half
    const int wg   = wid & 7;           // warp within half
    const int rg   = wg & 3;
    const int jc   = wg >> 2;
    const int b    = blockIdx.x >> 6;
    const int qt   = blockIdx.x & 63;
    const int n0   = b * LSEQ + qt * 64;
    const int gtid = tid & 255;

    int kt1 = qt - 4 * ph;
    int kt0 = kt1 - 3;
    if (kt0 < 0) kt0 = 0;
    const bool empty = (kt1 < kt0);

    // ---- Q tiles via cp.async: exactly 512 slots (64 rows x 8 chunks) ----
    {
        int s = tid;                     // 0..511, one slot per thread
        int r = s >> 3, c8 = (s & 7) << 3;
        uint32_t off = (uint32_t)(r * AS + c8) * 2;
        cpasync16(sb + OQH_A + off, &g_Qh[(size_t)(n0 + r) * DIM + c8]);
        cpasync16(sb + OQL_A + off, &g_Ql[(size_t)(n0 + r) * DIM + c8]);
    }
    // prologue: this half's kt0 tiles into its buf0 (commits Q loads too)
    const uint32_t kvbase = sb + OKV + (uint32_t)ph * PHSTR;
    if (!empty) {
        const int m0 = b * LSEQ + kt0 * 64;
        attn_prefetch_kv(kvbase, m0, m0 >> 6, gtid);
    } else {
        cp_commit();
    }
    cp_wait<0>();
    __syncthreads();     // Q visible to all; halves decouple from here

    float oacc[8][4];
#pragma unroll
    for (int d = 0; d < 8; d++)
#pragma unroll
        for (int c = 0; c < 4; c++) oacc[d][c] = 0.f;

    const int r0 = rg * 16 + (lane >> 2);
    const float gi0 = exp2f((float)r0 * LOG2GAMMA);
    const float gi1 = exp2f((float)(r0 + 8) * LOG2GAMMA);
    float gj[4][2];
#pragma unroll
    for (int jt = 0; jt < 4; jt++) {
        int j = jc * 32 + jt * 8 + ((lane & 3) << 1);
        gj[jt][0] = exp2f(-(float)j * LOG2GAMMA);
        gj[jt][1] = exp2f(-(float)(j + 1) * LOG2GAMMA);
    }

    const int lrow = lane & 15;
    const int lcg  = (lane >> 4) << 3;

    if (!empty)
    for (int kt = kt0; kt <= kt1; kt++) {
        const uint32_t kvb = kvbase + (uint32_t)((kt - kt0) & 1) * KVBUF;
        cp_wait<0>();
        bar_sync(ph + 1, 256);
        if (kt < kt1) {
            const int m0n = b * LSEQ + (kt + 1) * 64;
            attn_prefetch_kv(kvbase + (uint32_t)((kt - kt0 + 1) & 1) * KVBUF,
                             m0n, m0n >> 6, gtid);
        }

        // ---- S = Q K^T (3-term) ----
        float sfrag[4][4];
#pragma unroll
        for (int jt = 0; jt < 4; jt++)
#pragma unroll
            for (int c = 0; c < 4; c++) sfrag[jt][c] = 0.f;

#pragma unroll
        for (int ks = 0; ks < 4; ks++) {
            uint32_t aoff = (uint32_t)((rg * 16 + lrow) * AS + ks * 16 + lcg) * 2;
            uint32_t ah[4], al[4];
            ldsm4(ah, sb + OQH_A + aoff);
            ldsm4(al, sb + OQL_A + aoff);
            uint32_t bh[2][4], bl[2][4];
#pragma unroll
            for (int jg = 0; jg < 2; jg++) {
                uint32_t boff = (uint32_t)((jc * 32 + jg * 16 + lrow) * AS + ks * 16 + lcg) * 2;
                ldsm4(bh[jg], kvb + OFF_KH + boff);
                ldsm4(bl[jg], kvb + OFF_KL + boff);
            }
#pragma unroll
            for (int jt = 0; jt < 4; jt++) {
                int jg = jt >> 1, sel = jt & 1;
                uint32_t b0h = bh[jg][sel], b1h = bh[jg][sel + 2];
                uint32_t b0l = bl[jg][sel], b1l = bl[jg][sel + 2];
                mma_bf16(sfrag[jt], ah, b0h, b1h);
                mma_bf16(sfrag[jt], ah, b0l, b1l);
                mma_bf16(sfrag[jt], al, b0h, b1h);
            }
        }

        // ---- decay + mask + frag-direct hi/lo ----
        const float basekt = exp2f((float)((qt - kt) * 64) * LOG2GAMMA);
        uint32_t shh[2][4], sll[2][4];
#pragma unroll
        for (int jt = 0; jt < 4; jt++) {
            float w0 = basekt * gj[jt][0];
            float w1 = basekt * gj[jt][1];
            float v0 = sfrag[jt][0] * gi0 * w0;
            float v1 = sfrag[jt][1] * gi0 * w1;
            float v2 = sfrag[jt][2] * gi1 * w0;
            float v3 = sfrag[jt][3] * gi1 * w1;
            if (kt == qt) {
                int j0 = jc * 32 + jt * 8 + ((lane & 3) << 1);
                if (r0 < j0)         v0 = 0.f;
                if (r0 < j0 + 1)     v1 = 0.f;
                if (r0 + 8 < j0)     v2 = 0.f;
                if (r0 + 8 < j0 + 1) v3 = 0.f;
            }
            __nv_bfloat16 h0 = __float2bfloat16(v0);
            __nv_bfloat16 h1 = __float2bfloat16(v1);
            __nv_bfloat16 h2 = __float2bfloat16(v2);
            __nv_bfloat16 h3 = __float2bfloat16(v3);
            int ks2 = jt >> 1, odd = jt & 1;
            shh[ks2][odd * 2 + 0] = pack2(h0, h1);
            shh[ks2][odd * 2 + 1] = pack2(h2, h3);
            sll[ks2][odd * 2 + 0] =
                pack2(__float2bfloat16(v0 - __bfloat162float(h0)),
                      __float2bfloat16(v1 - __bfloat162float(h1)));
            sll[ks2][odd * 2 + 1] =
                pack2(__float2bfloat16(v2 - __bfloat162float(h2)),
                      __float2bfloat16(v3 - __bfloat162float(h3)));
        }

        // ---- O += S V (3-term) ----
#pragma unroll
        for (int ks2 = 0; ks2 < 2; ks2++) {
            uint32_t vbh[4][4], vbl[4][4];
#pragma unroll
            for (int dg = 0; dg < 4; dg++) {
                uint32_t voff = (uint32_t)((dg * 16 + lrow) * AS + jc * 32 + ks2 * 16 + lcg) * 2;
                ldsm4(vbh[dg], kvb + OFF_VH + voff);
                ldsm4(vbl[dg], kvb + OFF_VL + voff);
            }
#pragma unroll
            for (int dt = 0; dt < 8; dt++) {
                int dg = dt >> 1, sel = dt & 1;
                uint32_t b0h = vbh[dg][sel], b1h = vbh[dg][sel + 2];
                uint32_t b0l = vbl[dg][sel], b1l = vbl[dg][sel + 2];
                mma_bf16(oacc[dt], shh[ks2], b0h, b1h);
                mma_bf16(oacc[dt], sll[ks2], b0h, b1h);
                mma_bf16(oacc[dt], shh[ks2], b0l, b1l);
            }
        }
    }

    // ---- 4-group reduction: (jc, ph) groups 1..3 stage to smem, group 0 sums
    __syncthreads();
    const int grp = jc + 2 * ph;
    const int c2 = (lane & 3) << 1;
    float* red = (float*)sm;
    if (grp != 0) {
        float* rb = red + (size_t)(grp - 1) * (REDBUF / 4);
#pragma unroll
        for (int dt = 0; dt < 8; dt++) {
            int d = dt * 8 + c2;
            rb[r0 * RED_S + d]           = oacc[dt][0];
            rb[r0 * RED_S + d + 1]       = oacc[dt][1];
            rb[(r0 + 8) * RED_S + d]     = oacc[dt][2];
            rb[(r0 + 8) * RED_S + d + 1] = oacc[dt][3];
        }
    }
    __syncthreads();
    if (grp == 0) {
        float* r1 = red;
        float* r2 = red + (REDBUF / 4);
        float* r3 = red + 2 * (REDBUF / 4);
#pragma unroll
        for (int dt = 0; dt < 8; dt++) {
            int d = dt * 8 + c2;
            int lo = r0 * RED_S + d, hi = (r0 + 8) * RED_S + d;
            float2 a = make_float2(
                oacc[dt][0] + r1[lo] + r2[lo] + r3[lo],
                oacc[dt][1] + r1[lo + 1] + r2[lo + 1] + r3[lo + 1]);
            float2 bv = make_float2(
                oacc[dt][2] + r1[hi] + r2[hi] + r3[hi],
                oacc[dt][3] + r1[hi + 1] + r2[hi + 1] + r3[hi + 1]);
            *(float2*)&Out[(size_t)(n0 + r0) * DIM + d]     = a;
            *(float2*)&Out[(size_t)(n0 + r0 + 8) * DIM + d] = bv;
        }
    }
}

// ---------------------------------------------------------------------------
extern "C" void kernel_launch(void* const* d_in, const int* in_sizes, int n_in,
                              void* d_out, int out_size)
{
    const float* X  = (const float*)d_in[0];
    const float* Wq = (const float*)d_in[1];
    const float* Wk = (const float*)d_in[2];
    const float* Wv = (const float*)d_in[3];
    float* Out = (float*)d_out;

    cudaFuncSetAttribute(qkv_mma, cudaFuncAttributeMaxDynamicSharedMemorySize,
                         QKV_SMEM);
    cudaFuncSetAttribute(attn_mma, cudaFuncAttributeMaxDynamicSharedMemorySize,
                         ATTN_SMEM);

    prep_all<<<704, 256>>>(Wq, Wk, Wv);
    qkv_mma<<<NTOK / 64, 512, QKV_SMEM>>>(X);
    attn_mma<<<BATCH * (LSEQ / 64), 512, ATTN_SMEM>>>(Out);
}

// round 15
// speedup vs baseline: 1.4145x; 1.4145x over previous
#include <cuda_runtime.h>
#include <cuda_bf16.h>
#include <cuda_fp16.h>
#include <stdint.h>

#define BATCH 2
#define LSEQ  4096
#define HID   1024
#define DIM   64
#define NTOK  (BATCH * LSEQ)
#define LOG2GAMMA (-0.04580368961f)   /* log2(0.96875) */

// ---------------------------------------------------------------------------
// Device globals
// ---------------------------------------------------------------------------
__device__ __nv_bfloat16 g_Qh[NTOK * DIM];
__device__ __nv_bfloat16 g_Ql[NTOK * DIM];
__device__ __nv_bfloat16 g_Kh[NTOK * DIM];
__device__ __nv_bfloat16 g_Kl[NTOK * DIM];
__device__ __nv_bfloat16 g_Vth[NTOK * DIM];       // per-64-tile transposed [t][d][tok]
__device__ __nv_bfloat16 g_Vtl[NTOK * DIM];
__device__ float g_P[NTOK * DIM];                 // partial O from band half 1
__device__ int   g_flag[BATCH * 64];              // per (b,qt) handshake, stays 0
__device__ __half g_Whf[192 * HID];               // W^T concat [Q|K|V], fp16
__device__ float4 g_CO[LSEQ * 32];                // xPos coefs (cq,sq,ck,sk)

// ---------------------------------------------------------------------------
// Tensor-core helpers (sm_80+ portable)
// ---------------------------------------------------------------------------
__device__ __forceinline__ uint32_t smem_u32(const void* p) {
    uint32_t a;
    asm("{ .reg .u64 t; cvta.to.shared.u64 t, %1; cvt.u32.u64 %0, t; }"
        : "=r"(a) : "l"(p));
    return a;
}
__device__ __forceinline__ void ldsm4(uint32_t* r, uint32_t addr) {
    asm volatile("ldmatrix.sync.aligned.m8n8.x4.shared.b16 {%0,%1,%2,%3}, [%4];"
                 : "=r"(r[0]), "=r"(r[1]), "=r"(r[2]), "=r"(r[3]) : "r"(addr));
}
__device__ __forceinline__ void mma_bf16(float* d, const uint32_t* a,
                                         uint32_t b0, uint32_t b1) {
    asm volatile(
        "mma.sync.aligned.m16n8k16.row.col.f32.bf16.bf16.f32 "
        "{%0,%1,%2,%3},{%4,%5,%6,%7},{%8,%9},{%0,%1,%2,%3};"
        : "+f"(d[0]), "+f"(d[1]), "+f"(d[2]), "+f"(d[3])
        : "r"(a[0]), "r"(a[1]), "r"(a[2]), "r"(a[3]), "r"(b0), "r"(b1));
}
__device__ __forceinline__ void mma_f16(float* d, const uint32_t* a,
                                        uint32_t b0, uint32_t b1) {
    asm volatile(
        "mma.sync.aligned.m16n8k16.row.col.f32.f16.f16.f32 "
        "{%0,%1,%2,%3},{%4,%5,%6,%7},{%8,%9},{%0,%1,%2,%3};"
        : "+f"(d[0]), "+f"(d[1]), "+f"(d[2]), "+f"(d[3])
        : "r"(a[0]), "r"(a[1]), "r"(a[2]), "r"(a[3]), "r"(b0), "r"(b1));
}
__device__ __forceinline__ uint32_t pack2(__nv_bfloat16 a, __nv_bfloat16 b) {
    __nv_bfloat162 p = __halves2bfloat162(a, b);
    return *(uint32_t*)&p;
}
__device__ __forceinline__ uint32_t pack2h(__half a, __half b) {
    __half2 p = __halves2half2(a, b);
    return *(uint32_t*)&p;
}
__device__ __forceinline__ void cpasync16(uint32_t dst, const void* src) {
    asm volatile("cp.async.cg.shared.global [%0], [%1], 16;"
                 :: "r"(dst), "l"(src));
}
__device__ __forceinline__ void cp_commit() {
    asm volatile("cp.async.commit_group;" ::: "memory");
}
template <int N>
__device__ __forceinline__ void cp_wait() {
    asm volatile("cp.async.wait_group %0;" :: "n"(N) : "memory");
}

// ---------------------------------------------------------------------------
// Merged prep kernel.
// ---------------------------------------------------------------------------
__global__ __launch_bounds__(256) void prep_all(
    const float* __restrict__ Wq, const float* __restrict__ Wk,
    const float* __restrict__ Wv)
{
    __shared__ float t[32][33];
    if (blockIdx.x < 192) {
        const int tx = threadIdx.x & 31, ty = threadIdx.x >> 5;
        const int k0 = (blockIdx.x & 31) * 32;
        const int n0 = (blockIdx.x >> 5) * 32;
        const float* W = (n0 < 64) ? Wq : ((n0 < 128) ? Wk : Wv);
        const int ncol = n0 & 63;
#pragma unroll
        for (int i = 0; i < 4; i++) {
            int k = k0 + ty + i * 8;
            t[ty + i * 8][tx] = W[k * DIM + ncol + tx];
        }
        __syncthreads();
#pragma unroll
        for (int i = 0; i < 4; i++) {
            int n = n0 + ty + i * 8;
            g_Whf[(size_t)n * HID + k0 + tx] = __float2half_rn(t[tx][ty + i * 8]);
        }
    } else {
        int idx = (blockIdx.x - 192) * 256 + threadIdx.x;
        int l = idx >> 5;
        int i = idx & 31;
        float fl = (float)l;
        float inv_freq = exp2f(-(float)i * (13.287712379549449f / 32.0f));
        float sn, cs;
        sincosf(fl * inv_freq, &sn, &cs);
        float sv = ((float)(2 * i) + 25.6f) / 89.6f;
        float scq = exp2f(fl * (log2f(sv) * (1.0f / 512.0f)));
        g_CO[idx] = make_float4(cs * scq, sn * scq, cs / scq, sn / scq);
    }
}

// ---------------------------------------------------------------------------
// QKV projection, 2-term fp16 (unchanged from R12 / proven).
// ---------------------------------------------------------------------------
#define XS    72
#define XBUF  (2 * 64 * XS * 2)
#define OXL   (64 * XS * 2)
#define OW    (2 * XBUF)
#define WBUF  (192 * XS * 2)
#define QKV_SMEM (OW + 2 * WBUF)                  /* 92160 */

__global__ __launch_bounds__(512, 1) void qkv_mma(const float* __restrict__ X)
{
    extern __shared__ char smem[];
    const uint32_t sb = smem_u32(smem);
    const int tid  = threadIdx.x;
    const int lane = tid & 31;
    const int wid  = tid >> 5;
    const int mr   = (wid >> 2) * 16;
    const int nc   = (wid & 3) * 48;
    const int row0 = blockIdx.x * 64;

    const int xr = tid >> 3;
    const int xc = (tid & 7) << 2;
    const int wn0 = tid >> 3;
    const int wc8 = (tid & 7) << 3;

    float acc[6][4];
#pragma unroll
    for (int b = 0; b < 6; b++)
#pragma unroll
        for (int c = 0; c < 4; c++) acc[b][c] = 0.f;

    {
#pragma unroll
        for (int it = 0; it < 3; it++) {
            int n = wn0 + it * 64;
            cpasync16(sb + OW + (uint32_t)(n * XS + wc8) * 2, &g_Whf[n * HID + wc8]);
        }
        cp_commit();
#pragma unroll
        for (int it = 0; it < 2; it++) {
            int c = xc + it * 32;
            float4 x = *(const float4*)&X[(size_t)(row0 + xr) * HID + c];
            __half hx = __float2half_rn(x.x);
            __half hy = __float2half_rn(x.y);
            __half hz = __float2half_rn(x.z);
            __half hw = __float2half_rn(x.w);
            uint32_t off = (uint32_t)(xr * XS + c) * 2;
            *(uint2*)(smem + off)       = make_uint2(pack2h(hx, hy), pack2h(hz, hw));
            *(uint2*)(smem + OXL + off) = make_uint2(
                pack2h(__float2half_rn(x.x - __half2float(hx)),
                       __float2half_rn(x.y - __half2float(hy))),
                pack2h(__float2half_rn(x.z - __half2float(hz)),
                       __float2half_rn(x.w - __half2float(hw))));
        }
    }

    for (int ch = 0; ch < 16; ch++) {
        const uint32_t xb = sb + (uint32_t)(ch & 1) * XBUF;
        const uint32_t wb = sb + OW + (uint32_t)(ch & 1) * WBUF;
        cp_wait<0>();
        __syncthreads();

        float4 xpre[2];
        if (ch < 15) {
            const int kcn = (ch + 1) * 64;
            uint32_t wbn = sb + OW + (uint32_t)((ch + 1) & 1) * WBUF;
#pragma unroll
            for (int it = 0; it < 3; it++) {
                int n = wn0 + it * 64;
                cpasync16(wbn + (uint32_t)(n * XS + wc8) * 2,
                          &g_Whf[n * HID + kcn + wc8]);
            }
            cp_commit();
#pragma unroll
            for (int it = 0; it < 2; it++)
                xpre[it] = *(const float4*)&X[(size_t)(row0 + xr) * HID + kcn + xc + it * 32];
        }

        const int lrow = lane & 15;
        const int lcg  = (lane >> 4) << 3;
#pragma unroll
        for (int ks = 0; ks < 4; ks++) {
            const int lcol = ks * 16 + lcg;
            uint32_t ah[4], al[4], bh[3][4];
            {
                uint32_t off = (uint32_t)((mr + lrow) * XS + lcol) * 2;
                ldsm4(ah, xb + off);
                ldsm4(al, xb + OXL + off);
            }
#pragma unroll
            for (int nf = 0; nf < 3; nf++) {
                uint32_t off = (uint32_t)((nc + nf * 16 + lrow) * XS + lcol) * 2;
                ldsm4(bh[nf], wb + off);
            }
#pragma unroll
            for (int nf = 0; nf < 3; nf++) {
                mma_f16(acc[nf * 2],     ah, bh[nf][0], bh[nf][2]);
                mma_f16(acc[nf * 2],     al, bh[nf][0], bh[nf][2]);
                mma_f16(acc[nf * 2 + 1], ah, bh[nf][1], bh[nf][3]);
                mma_f16(acc[nf * 2 + 1], al, bh[nf][1], bh[nf][3]);
            }
        }

        if (ch < 15) {
            char* xdn = smem + (size_t)((ch + 1) & 1) * XBUF;
#pragma unroll
            for (int it = 0; it < 2; it++) {
                int c = xc + it * 32;
                float4 x = xpre[it];
                __half hx = __float2half_rn(x.x);
                __half hy = __float2half_rn(x.y);
                __half hz = __float2half_rn(x.z);
                __half hw = __float2half_rn(x.w);
                uint32_t off = (uint32_t)(xr * XS + c) * 2;
                *(uint2*)(xdn + off)       = make_uint2(pack2h(hx, hy), pack2h(hz, hw));
                *(uint2*)(xdn + OXL + off) = make_uint2(
                    pack2h(__float2half_rn(x.x - __half2float(hx)),
                           __float2half_rn(x.y - __half2float(hy))),
                    pack2h(__float2half_rn(x.z - __half2float(hz)),
                           __float2half_rn(x.w - __half2float(hw))));
            }
        }
    }

    const int r4 = lane >> 2;
    const int c2 = (lane & 3) * 2;
#pragma unroll
    for (int h2 = 0; h2 < 2; h2++) {
        int g = row0 + mr + h2 * 8 + r4;
        int l = g & (LSEQ - 1);
#pragma unroll
        for (int nf = 0; nf < 6; nf++) {
            int col0 = nc + nf * 8;
            int mat  = col0 >> 6;
            int lcol = (col0 & 63) + c2;
            float v0 = acc[nf][h2 * 2 + 0];
            float v1 = acc[nf][h2 * 2 + 1];
            if (mat == 0) {
                float4 co = g_CO[l * 32 + (lcol >> 1)];
                float o0 = v0 * co.x - v1 * co.y;
                float o1 = v1 * co.x + v0 * co.y;
                __nv_bfloat16 h0 = __float2bfloat16(o0);
                __nv_bfloat16 h1 = __float2bfloat16(o1);
                *(uint32_t*)&g_Qh[g * DIM + lcol] = pack2(h0, h1);
                *(uint32_t*)&g_Ql[g * DIM + lcol] =
                    pack2(__float2bfloat16(o0 - __bfloat162float(h0)),
                          __float2bfloat16(o1 - __bfloat162float(h1)));
            } else if (mat == 1) {
                float4 co = g_CO[l * 32 + (lcol >> 1)];
                float o0 = v0 * co.z - v1 * co.w;
                float o1 = v1 * co.z + v0 * co.w;
                __nv_bfloat16 h0 = __float2bfloat16(o0);
                __nv_bfloat16 h1 = __float2bfloat16(o1);
                *(uint32_t*)&g_Kh[g * DIM + lcol] = pack2(h0, h1);
                *(uint32_t*)&g_Kl[g * DIM + lcol] =
                    pack2(__float2bfloat16(o0 - __bfloat162float(h0)),
                          __float2bfloat16(o1 - __bfloat162float(h1)));
            } else {
                int t = g >> 6, tok = g & 63;
                __nv_bfloat16 h0 = __float2bfloat16(v0);
                __nv_bfloat16 h1 = __float2bfloat16(v1);
                g_Vth[t * 4096 + lcol * 64 + tok]       = h0;
                g_Vth[t * 4096 + (lcol + 1) * 64 + tok] = h1;
                g_Vtl[t * 4096 + lcol * 64 + tok] =
                    __float2bfloat16(v0 - __bfloat162float(h0));
                g_Vtl[t * 4096 + (lcol + 1) * 64 + tok] =
                    __float2bfloat16(v1 - __bfloat162float(h1));
            }
        }
    }
}

// ---------------------------------------------------------------------------
// Banded decay attention (R12 pipeline), combine fused via flag handshake:
//   p=0: kt in [qt-3, qt]   -> waits for partner flag, adds g_P, writes Out
//   p=1: kt in [qt-6, qt-4] -> writes g_P, threadfence, sets flag
// Grid 256 x 256 threads. Band now 7 tiles (min excluded diff 385).
// ---------------------------------------------------------------------------
#define AS     72
#define TILE_B (64 * AS * 2)               /* 9216 */
#define OQH_A  0
#define OQL_A  TILE_B
#define OKV    (2 * TILE_B)                /* 18432 */
#define KVBUF  (4 * TILE_B)                /* 36864: KH, KL, VH, VL */
#define OFF_KH 0
#define OFF_KL TILE_B
#define OFF_VH (2 * TILE_B)
#define OFF_VL (3 * TILE_B)
#define ATTN_SMEM (OKV + 2 * KVBUF)        /* 92160 */
#define RED_S  68

__device__ __forceinline__ void attn_prefetch_kv(
    uint32_t kvb, int m0, int tile, int tid)
{
#pragma unroll
    for (int it = 0; it < 2; it++) {
        int s = it * 256 + tid;
        int r = s >> 3, c8 = (s & 7) << 3;
        uint32_t off = (uint32_t)(r * AS + c8) * 2;
        cpasync16(kvb + OFF_KH + off, &g_Kh[(size_t)(m0 + r) * DIM + c8]);
        cpasync16(kvb + OFF_KL + off, &g_Kl[(size_t)(m0 + r) * DIM + c8]);
        cpasync16(kvb + OFF_VH + off, &g_Vth[(size_t)tile * 4096 + r * 64 + c8]);
        cpasync16(kvb + OFF_VL + off, &g_Vtl[(size_t)tile * 4096 + r * 64 + c8]);
    }
    cp_commit();
}

__global__ __launch_bounds__(256) void attn_mma(float* __restrict__ Out)
{
    extern __shared__ char sm[];
    const uint32_t sb = smem_u32(sm);
    const int tid  = threadIdx.x;
    const int lane = tid & 31;
    const int wid  = tid >> 5;
    const int rg   = wid & 3;
    const int jc   = wid >> 2;
    const int p    = blockIdx.x >> 7;
    const int b    = (blockIdx.x >> 6) & 1;
    const int qt   = blockIdx.x & 63;
    const int n0   = b * LSEQ + qt * 64;
    const int fidx = blockIdx.x & 127;

    int kt0, kt1;
    if (p == 0) { kt0 = qt - 3; if (kt0 < 0) kt0 = 0; kt1 = qt; }
    else        { kt0 = qt - 6; if (kt0 < 0) kt0 = 0; kt1 = qt - 4; }

    if (kt1 < kt0) return;   // only p=1 with qt<4; p=0 partner skips the wait

    // Q tiles (plain LDG/STS; covered by first sync)
#pragma unroll
    for (int it = 0; it < 2; it++) {
        int s = it * 256 + tid;
        int r = s >> 3, c8 = (s & 7) << 3;
        uint32_t off = (uint32_t)(r * AS + c8) * 2;
        *(uint4*)(sm + OQH_A + off) = *(const uint4*)&g_Qh[(size_t)(n0 + r) * DIM + c8];
        *(uint4*)(sm + OQL_A + off) = *(const uint4*)&g_Ql[(size_t)(n0 + r) * DIM + c8];
    }

    // prologue: prefetch kt0 tiles into buf0
    {
        const int m0 = b * LSEQ + kt0 * 64;
        attn_prefetch_kv(sb + OKV, m0, m0 >> 6, tid);
    }

    float oacc[8][4];
#pragma unroll
    for (int d = 0; d < 8; d++)
#pragma unroll
        for (int c = 0; c < 4; c++) oacc[d][c] = 0.f;

    const int r0 = rg * 16 + (lane >> 2);
    const float gi0 = exp2f((float)r0 * LOG2GAMMA);
    const float gi1 = exp2f((float)(r0 + 8) * LOG2GAMMA);
    float gj[4][2];
#pragma unroll
    for (int jt = 0; jt < 4; jt++) {
        int j = jc * 32 + jt * 8 + ((lane & 3) << 1);
        gj[jt][0] = exp2f(-(float)j * LOG2GAMMA);
        gj[jt][1] = exp2f(-(float)(j + 1) * LOG2GAMMA);
    }

    const int lrow = lane & 15;
    const int lcg  = (lane >> 4) << 3;

    for (int kt = kt0; kt <= kt1; kt++) {
        const uint32_t kvb = sb + OKV + (uint32_t)((kt - kt0) & 1) * KVBUF;
        cp_wait<0>();
        __syncthreads();
        if (kt < kt1) {
            const int m0n = b * LSEQ + (kt + 1) * 64;
            attn_prefetch_kv(sb + OKV + (uint32_t)((kt - kt0 + 1) & 1) * KVBUF,
                             m0n, m0n >> 6, tid);
        }

        // ---- S = Q K^T (3-term) ----
        float sfrag[4][4];
#pragma unroll
        for (int jt = 0; jt < 4; jt++)
#pragma unroll
            for (int c = 0; c < 4; c++) sfrag[jt][c] = 0.f;

#pragma unroll
        for (int ks = 0; ks < 4; ks++) {
            uint32_t aoff = (uint32_t)((rg * 16 + lrow) * AS + ks * 16 + lcg) * 2;
            uint32_t ah[4], al[4];
            ldsm4(ah, sb + OQH_A + aoff);
            ldsm4(al, sb + OQL_A + aoff);
            uint32_t bh[2][4], bl[2][4];
#pragma unroll
            for (int jg = 0; jg < 2; jg++) {
                uint32_t boff = (uint32_t)((jc * 32 + jg * 16 + lrow) * AS + ks * 16 + lcg) * 2;
                ldsm4(bh[jg], kvb + OFF_KH + boff);
                ldsm4(bl[jg], kvb + OFF_KL + boff);
            }
#pragma unroll
            for (int jt = 0; jt < 4; jt++) {
                int jg = jt >> 1, sel = jt & 1;
                uint32_t b0h = bh[jg][sel], b1h = bh[jg][sel + 2];
                uint32_t b0l = bl[jg][sel], b1l = bl[jg][sel + 2];
                mma_bf16(sfrag[jt], ah, b0h, b1h);
                mma_bf16(sfrag[jt], ah, b0l, b1l);
                mma_bf16(sfrag[jt], al, b0h, b1h);
            }
        }

        // ---- decay + mask + frag-direct hi/lo conversion ----
        const float basekt = exp2f((float)((qt - kt) * 64) * LOG2GAMMA);
        uint32_t shh[2][4], sll[2][4];
#pragma unroll
        for (int jt = 0; jt < 4; jt++) {
            float w0 = basekt * gj[jt][0];
            float w1 = basekt * gj[jt][1];
            float v0 = sfrag[jt][0] * gi0 * w0;
            float v1 = sfrag[jt][1] * gi0 * w1;
            float v2 = sfrag[jt][2] * gi1 * w0;
            float v3 = sfrag[jt][3] * gi1 * w1;
            if (kt == qt) {
                int j0 = jc * 32 + jt * 8 + ((lane & 3) << 1);
                if (r0 < j0)         v0 = 0.f;
                if (r0 < j0 + 1)     v1 = 0.f;
                if (r0 + 8 < j0)     v2 = 0.f;
                if (r0 + 8 < j0 + 1) v3 = 0.f;
            }
            __nv_bfloat16 h0 = __float2bfloat16(v0);
            __nv_bfloat16 h1 = __float2bfloat16(v1);
            __nv_bfloat16 h2 = __float2bfloat16(v2);
            __nv_bfloat16 h3 = __float2bfloat16(v3);
            int ks2 = jt >> 1, odd = jt & 1;
            shh[ks2][odd * 2 + 0] = pack2(h0, h1);
            shh[ks2][odd * 2 + 1] = pack2(h2, h3);
            sll[ks2][odd * 2 + 0] =
                pack2(__float2bfloat16(v0 - __bfloat162float(h0)),
                      __float2bfloat16(v1 - __bfloat162float(h1)));
            sll[ks2][odd * 2 + 1] =
                pack2(__float2bfloat16(v2 - __bfloat162float(h2)),
                      __float2bfloat16(v3 - __bfloat162float(h3)));
        }

        // ---- O += S V (3-term) ----
#pragma unroll
        for (int ks2 = 0; ks2 < 2; ks2++) {
            uint32_t vbh[4][4], vbl[4][4];
#pragma unroll
            for (int dg = 0; dg < 4; dg++) {
                uint32_t voff = (uint32_t)((dg * 16 + lrow) * AS + jc * 32 + ks2 * 16 + lcg) * 2;
                ldsm4(vbh[dg], kvb + OFF_VH + voff);
                ldsm4(vbl[dg], kvb + OFF_VL + voff);
            }
#pragma unroll
            for (int dt = 0; dt < 8; dt++) {
                int dg = dt >> 1, sel = dt & 1;
                uint32_t b0h = vbh[dg][sel], b1h = vbh[dg][sel + 2];
                uint32_t b0l = vbl[dg][sel], b1l = vbl[dg][sel + 2];
                mma_bf16(oacc[dt], shh[ks2], b0h, b1h);
                mma_bf16(oacc[dt], sll[ks2], b0h, b1h);
                mma_bf16(oacc[dt], shh[ks2], b0l, b1l);
            }
        }
    }

    // ---- pair reduction (jc) over smem ----
    __syncthreads();
    float* red = (float*)sm;                 // reuses Q area
    const int c2 = (lane & 3) << 1;
    if (jc == 1) {
#pragma unroll
        for (int dt = 0; dt < 8; dt++) {
            int d = dt * 8 + c2;
            red[r0 * RED_S + d]           = oacc[dt][0];
            red[r0 * RED_S + d + 1]       = oacc[dt][1];
            red[(r0 + 8) * RED_S + d]     = oacc[dt][2];
            red[(r0 + 8) * RED_S + d + 1] = oacc[dt][3];
        }
    }
    __syncthreads();

    if (p == 1) {
        // publish partial to g_P, then release the flag
        if (jc == 0) {
#pragma unroll
            for (int dt = 0; dt < 8; dt++) {
                int d = dt * 8 + c2;
                float2 lo = make_float2(oacc[dt][0] + red[r0 * RED_S + d],
                                        oacc[dt][1] + red[r0 * RED_S + d + 1]);
                float2 hi = make_float2(oacc[dt][2] + red[(r0 + 8) * RED_S + d],
                                        oacc[dt][3] + red[(r0 + 8) * RED_S + d + 1]);
                *(float2*)&g_P[(size_t)(n0 + r0) * DIM + d]     = lo;
                *(float2*)&g_P[(size_t)(n0 + r0 + 8) * DIM + d] = hi;
            }
        }
        __threadfence();
        __syncthreads();
        if (tid == 0) atomicExch(&g_flag[fidx], 1);
    } else {
        const bool have_partner = (qt >= 4);
        if (have_partner) {
            if (tid == 0) {
                while (atomicOr(&g_flag[fidx], 0) == 0) __nanosleep(64);
                atomicExch(&g_flag[fidx], 0);     // reset for next launch
                __threadfence();
            }
            __syncthreads();
        }
        if (jc == 0) {
#pragma unroll
            for (int dt = 0; dt < 8; dt++) {
                int d = dt * 8 + c2;
                float2 lo = make_float2(oacc[dt][0] + red[r0 * RED_S + d],
                                        oacc[dt][1] + red[r0 * RED_S + d + 1]);
                float2 hi = make_float2(oacc[dt][2] + red[(r0 + 8) * RED_S + d],
                                        oacc[dt][3] + red[(r0 + 8) * RED_S + d + 1]);
                if (have_partner) {
                    float2 plo = *(const float2*)&g_P[(size_t)(n0 + r0) * DIM + d];
                    float2 phi = *(const float2*)&g_P[(size_t)(n0 + r0 + 8) * DIM + d];
                    lo.x += plo.x; lo.y += plo.y;
                    hi.x += phi.x; hi.y += phi.y;
                }
                *(float2*)&Out[(size_t)(n0 + r0) * DIM + d]     = lo;
                *(float2*)&Out[(size_t)(n0 + r0 + 8) * DIM + d] = hi;
            }
        }
    }
}

// ---------------------------------------------------------------------------
extern "C" void kernel_launch(void* const* d_in, const int* in_sizes, int n_in,
                              void* d_out, int out_size)
{
    const float* X  = (const float*)d_in[0];
    const float* Wq = (const float*)d_in[1];
    const float* Wk = (const float*)d_in[2];
    const float* Wv = (const float*)d_in[3];
    float* Out = (float*)d_out;

    cudaFuncSetAttribute(qkv_mma, cudaFuncAttributeMaxDynamicSharedMemorySize,
                         QKV_SMEM);
    cudaFuncSetAttribute(attn_mma, cudaFuncAttributeMaxDynamicSharedMemorySize,
                         ATTN_SMEM);

    prep_all<<<704, 256>>>(Wq, Wk, Wv);
    qkv_mma<<<NTOK / 64, 512, QKV_SMEM>>>(X);
    attn_mma<<<2 * BATCH * (LSEQ / 64), 256, ATTN_SMEM>>>(Out);
}

// round 16
// speedup vs baseline: 1.4886x; 1.0523x over previous
#include <cuda_runtime.h>
#include <cuda_bf16.h>
#include <cuda_fp16.h>
#include <stdint.h>

#define BATCH 2
#define LSEQ  4096
#define HID   1024
#define DIM   64
#define NTOK  (BATCH * LSEQ)
#define LOG2GAMMA (-0.04580368961f)   /* log2(0.96875) */

// ---------------------------------------------------------------------------
// Device globals
// ---------------------------------------------------------------------------
__device__ __nv_bfloat16 g_Qh[NTOK * DIM];
__device__ __nv_bfloat16 g_Ql[NTOK * DIM];
__device__ __nv_bfloat16 g_Kh[NTOK * DIM];
__device__ __nv_bfloat16 g_Kl[NTOK * DIM];
__device__ __nv_bfloat16 g_Vth[NTOK * DIM];       // per-64-tile transposed [t][d][tok]
__device__ __nv_bfloat16 g_Vtl[NTOK * DIM];
__device__ __half g_Whf[192 * HID];               // W^T concat [Q|K|V], fp16
__device__ float4 g_CO[LSEQ * 32];                // xPos coefs (cq,sq,ck,sk)

// ---------------------------------------------------------------------------
// Tensor-core helpers (sm_80+ portable)
// ---------------------------------------------------------------------------
__device__ __forceinline__ uint32_t smem_u32(const void* p) {
    uint32_t a;
    asm("{ .reg .u64 t; cvta.to.shared.u64 t, %1; cvt.u32.u64 %0, t; }"
        : "=r"(a) : "l"(p));
    return a;
}
__device__ __forceinline__ void ldsm4(uint32_t* r, uint32_t addr) {
    asm volatile("ldmatrix.sync.aligned.m8n8.x4.shared.b16 {%0,%1,%2,%3}, [%4];"
                 : "=r"(r[0]), "=r"(r[1]), "=r"(r[2]), "=r"(r[3]) : "r"(addr));
}
__device__ __forceinline__ void mma_bf16(float* d, const uint32_t* a,
                                         uint32_t b0, uint32_t b1) {
    asm volatile(
        "mma.sync.aligned.m16n8k16.row.col.f32.bf16.bf16.f32 "
        "{%0,%1,%2,%3},{%4,%5,%6,%7},{%8,%9},{%0,%1,%2,%3};"
        : "+f"(d[0]), "+f"(d[1]), "+f"(d[2]), "+f"(d[3])
        : "r"(a[0]), "r"(a[1]), "r"(a[2]), "r"(a[3]), "r"(b0), "r"(b1));
}
__device__ __forceinline__ void mma_f16(float* d, const uint32_t* a,
                                        uint32_t b0, uint32_t b1) {
    asm volatile(
        "mma.sync.aligned.m16n8k16.row.col.f32.f16.f16.f32 "
        "{%0,%1,%2,%3},{%4,%5,%6,%7},{%8,%9},{%0,%1,%2,%3};"
        : "+f"(d[0]), "+f"(d[1]), "+f"(d[2]), "+f"(d[3])
        : "r"(a[0]), "r"(a[1]), "r"(a[2]), "r"(a[3]), "r"(b0), "r"(b1));
}
__device__ __forceinline__ uint32_t pack2(__nv_bfloat16 a, __nv_bfloat16 b) {
    __nv_bfloat162 p = __halves2bfloat162(a, b);
    return *(uint32_t*)&p;
}
__device__ __forceinline__ uint32_t pack2h(__half a, __half b) {
    __half2 p = __halves2half2(a, b);
    return *(uint32_t*)&p;
}
__device__ __forceinline__ void cpasync16(uint32_t dst, const void* src) {
    asm volatile("cp.async.cg.shared.global [%0], [%1], 16;"
                 :: "r"(dst), "l"(src));
}
__device__ __forceinline__ void cp_commit() {
    asm volatile("cp.async.commit_group;" ::: "memory");
}
template <int N>
__device__ __forceinline__ void cp_wait() {
    asm volatile("cp.async.wait_group %0;" :: "n"(N) : "memory");
}

// ---------------------------------------------------------------------------
// Merged prep kernel (compacted: 256 blocks).
//  blocks [0,192):   W^T concat -> fp16, coalesced 32x32 smem transpose
//  blocks [192,256): xPos coef table, 8 elements per thread
// ---------------------------------------------------------------------------
__global__ __launch_bounds__(256) void prep_all(
    const float* __restrict__ Wq, const float* __restrict__ Wk,
    const float* __restrict__ Wv)
{
    __shared__ float t[32][33];
    if (blockIdx.x < 192) {
        const int tx = threadIdx.x & 31, ty = threadIdx.x >> 5;
        const int k0 = (blockIdx.x & 31) * 32;
        const int n0 = (blockIdx.x >> 5) * 32;
        const float* W = (n0 < 64) ? Wq : ((n0 < 128) ? Wk : Wv);
        const int ncol = n0 & 63;
#pragma unroll
        for (int i = 0; i < 4; i++) {
            int k = k0 + ty + i * 8;
            t[ty + i * 8][tx] = W[k * DIM + ncol + tx];
        }
        __syncthreads();
#pragma unroll
        for (int i = 0; i < 4; i++) {
            int n = n0 + ty + i * 8;
            g_Whf[(size_t)n * HID + k0 + tx] = __float2half_rn(t[tx][ty + i * 8]);
        }
    } else {
        int base = (blockIdx.x - 192) * 2048;
#pragma unroll
        for (int e = 0; e < 8; e++) {
            int idx = base + e * 256 + threadIdx.x;
            int l = idx >> 5;
            int i = idx & 31;
            float fl = (float)l;
            float inv_freq = exp2f(-(float)i * (13.287712379549449f / 32.0f));
            float sn, cs;
            sincosf(fl * inv_freq, &sn, &cs);
            float sv = ((float)(2 * i) + 25.6f) / 89.6f;
            float scq = exp2f(fl * (log2f(sv) * (1.0f / 512.0f)));
            g_CO[idx] = make_float4(cs * scq, sn * scq, cs / scq, sn / scq);
        }
    }
}

// ---------------------------------------------------------------------------
// QKV projection, 2-term fp16 (unchanged from R12 / proven).
// ---------------------------------------------------------------------------
#define XS    72
#define XBUF  (2 * 64 * XS * 2)
#define OXL   (64 * XS * 2)
#define OW    (2 * XBUF)
#define WBUF  (192 * XS * 2)
#define QKV_SMEM (OW + 2 * WBUF)                  /* 92160 */

__global__ __launch_bounds__(512, 1) void qkv_mma(const float* __restrict__ X)
{
    extern __shared__ char smem[];
    const uint32_t sb = smem_u32(smem);
    const int tid  = threadIdx.x;
    const int lane = tid & 31;
    const int wid  = tid >> 5;
    const int mr   = (wid >> 2) * 16;
    const int nc   = (wid & 3) * 48;
    const int row0 = blockIdx.x * 64;

    const int xr = tid >> 3;
    const int xc = (tid & 7) << 2;
    const int wn0 = tid >> 3;
    const int wc8 = (tid & 7) << 3;

    float acc[6][4];
#pragma unroll
    for (int b = 0; b < 6; b++)
#pragma unroll
        for (int c = 0; c < 4; c++) acc[b][c] = 0.f;

    {
#pragma unroll
        for (int it = 0; it < 3; it++) {
            int n = wn0 + it * 64;
            cpasync16(sb + OW + (uint32_t)(n * XS + wc8) * 2, &g_Whf[n * HID + wc8]);
        }
        cp_commit();
#pragma unroll
        for (int it = 0; it < 2; it++) {
            int c = xc + it * 32;
            float4 x = *(const float4*)&X[(size_t)(row0 + xr) * HID + c];
            __half hx = __float2half_rn(x.x);
            __half hy = __float2half_rn(x.y);
            __half hz = __float2half_rn(x.z);
            __half hw = __float2half_rn(x.w);
            uint32_t off = (uint32_t)(xr * XS + c) * 2;
            *(uint2*)(smem + off)       = make_uint2(pack2h(hx, hy), pack2h(hz, hw));
            *(uint2*)(smem + OXL + off) = make_uint2(
                pack2h(__float2half_rn(x.x - __half2float(hx)),
                       __float2half_rn(x.y - __half2float(hy))),
                pack2h(__float2half_rn(x.z - __half2float(hz)),
                       __float2half_rn(x.w - __half2float(hw))));
        }
    }

    for (int ch = 0; ch < 16; ch++) {
        const uint32_t xb = sb + (uint32_t)(ch & 1) * XBUF;
        const uint32_t wb = sb + OW + (uint32_t)(ch & 1) * WBUF;
        cp_wait<0>();
        __syncthreads();

        float4 xpre[2];
        if (ch < 15) {
            const int kcn = (ch + 1) * 64;
            uint32_t wbn = sb + OW + (uint32_t)((ch + 1) & 1) * WBUF;
#pragma unroll
            for (int it = 0; it < 3; it++) {
                int n = wn0 + it * 64;
                cpasync16(wbn + (uint32_t)(n * XS + wc8) * 2,
                          &g_Whf[n * HID + kcn + wc8]);
            }
            cp_commit();
#pragma unroll
            for (int it = 0; it < 2; it++)
                xpre[it] = *(const float4*)&X[(size_t)(row0 + xr) * HID + kcn + xc + it * 32];
        }

        const int lrow = lane & 15;
        const int lcg  = (lane >> 4) << 3;
#pragma unroll
        for (int ks = 0; ks < 4; ks++) {
            const int lcol = ks * 16 + lcg;
            uint32_t ah[4], al[4], bh[3][4];
            {
                uint32_t off = (uint32_t)((mr + lrow) * XS + lcol) * 2;
                ldsm4(ah, xb + off);
                ldsm4(al, xb + OXL + off);
            }
#pragma unroll
            for (int nf = 0; nf < 3; nf++) {
                uint32_t off = (uint32_t)((nc + nf * 16 + lrow) * XS + lcol) * 2;
                ldsm4(bh[nf], wb + off);
            }
#pragma unroll
            for (int nf = 0; nf < 3; nf++) {
                mma_f16(acc[nf * 2],     ah, bh[nf][0], bh[nf][2]);
                mma_f16(acc[nf * 2],     al, bh[nf][0], bh[nf][2]);
                mma_f16(acc[nf * 2 + 1], ah, bh[nf][1], bh[nf][3]);
                mma_f16(acc[nf * 2 + 1], al, bh[nf][1], bh[nf][3]);
            }
        }

        if (ch < 15) {
            char* xdn = smem + (size_t)((ch + 1) & 1) * XBUF;
#pragma unroll
            for (int it = 0; it < 2; it++) {
                int c = xc + it * 32;
                float4 x = xpre[it];
                __half hx = __float2half_rn(x.x);
                __half hy = __float2half_rn(x.y);
                __half hz = __float2half_rn(x.z);
                __half hw = __float2half_rn(x.w);
                uint32_t off = (uint32_t)(xr * XS + c) * 2;
                *(uint2*)(xdn + off)       = make_uint2(pack2h(hx, hy), pack2h(hz, hw));
                *(uint2*)(xdn + OXL + off) = make_uint2(
                    pack2h(__float2half_rn(x.x - __half2float(hx)),
                           __float2half_rn(x.y - __half2float(hy))),
                    pack2h(__float2half_rn(x.z - __half2float(hz)),
                           __float2half_rn(x.w - __half2float(hw))));
            }
        }
    }

    const int r4 = lane >> 2;
    const int c2 = (lane & 3) * 2;
#pragma unroll
    for (int h2 = 0; h2 < 2; h2++) {
        int g = row0 + mr + h2 * 8 + r4;
        int l = g & (LSEQ - 1);
#pragma unroll
        for (int nf = 0; nf < 6; nf++) {
            int col0 = nc + nf * 8;
            int mat  = col0 >> 6;
            int lcol = (col0 & 63) + c2;
            float v0 = acc[nf][h2 * 2 + 0];
            float v1 = acc[nf][h2 * 2 + 1];
            if (mat == 0) {
                float4 co = g_CO[l * 32 + (lcol >> 1)];
                float o0 = v0 * co.x - v1 * co.y;
                float o1 = v1 * co.x + v0 * co.y;
                __nv_bfloat16 h0 = __float2bfloat16(o0);
                __nv_bfloat16 h1 = __float2bfloat16(o1);
                *(uint32_t*)&g_Qh[g * DIM + lcol] = pack2(h0, h1);
                *(uint32_t*)&g_Ql[g * DIM + lcol] =
                    pack2(__float2bfloat16(o0 - __bfloat162float(h0)),
                          __float2bfloat16(o1 - __bfloat162float(h1)));
            } else if (mat == 1) {
                float4 co = g_CO[l * 32 + (lcol >> 1)];
                float o0 = v0 * co.z - v1 * co.w;
                float o1 = v1 * co.z + v0 * co.w;
                __nv_bfloat16 h0 = __float2bfloat16(o0);
                __nv_bfloat16 h1 = __float2bfloat16(o1);
                *(uint32_t*)&g_Kh[g * DIM + lcol] = pack2(h0, h1);
                *(uint32_t*)&g_Kl[g * DIM + lcol] =
                    pack2(__float2bfloat16(o0 - __bfloat162float(h0)),
                          __float2bfloat16(o1 - __bfloat162float(h1)));
            } else {
                int t = g >> 6, tok = g & 63;
                __nv_bfloat16 h0 = __float2bfloat16(v0);
                __nv_bfloat16 h1 = __float2bfloat16(v1);
                g_Vth[t * 4096 + lcol * 64 + tok]       = h0;
                g_Vth[t * 4096 + (lcol + 1) * 64 + tok] = h1;
                g_Vtl[t * 4096 + lcol * 64 + tok] =
                    __float2bfloat16(v0 - __bfloat162float(h0));
                g_Vtl[t * 4096 + (lcol + 1) * 64 + tok] =
                    __float2bfloat16(v1 - __bfloat162float(h1));
            }
        }
    }
}

// ---------------------------------------------------------------------------
// Banded decay attention: ONE 256-thread block per (b, qt), grid 128
// (single balanced wave on 148 SMs). Band 6 tiles: kt in [qt-5, qt]
// (min excluded diff 321, gamma^321 = 3.7e-5 — negligible).
// cp.async double-buffered kt pipeline; 3-term bf16 numerics (proven).
// ---------------------------------------------------------------------------
#define AS     72
#define TILE_B (64 * AS * 2)               /* 9216 */
#define OQH_A  0
#define OQL_A  TILE_B
#define OKV    (2 * TILE_B)                /* 18432 */
#define KVBUF  (4 * TILE_B)                /* 36864: KH, KL, VH, VL */
#define OFF_KH 0
#define OFF_KL TILE_B
#define OFF_VH (2 * TILE_B)
#define OFF_VL (3 * TILE_B)
#define ATTN_SMEM (OKV + 2 * KVBUF)        /* 92160 */
#define RED_S  68

__device__ __forceinline__ void attn_prefetch_kv(
    uint32_t kvb, int m0, int tile, int tid)
{
#pragma unroll
    for (int it = 0; it < 2; it++) {
        int s = it * 256 + tid;
        int r = s >> 3, c8 = (s & 7) << 3;
        uint32_t off = (uint32_t)(r * AS + c8) * 2;
        cpasync16(kvb + OFF_KH + off, &g_Kh[(size_t)(m0 + r) * DIM + c8]);
        cpasync16(kvb + OFF_KL + off, &g_Kl[(size_t)(m0 + r) * DIM + c8]);
        cpasync16(kvb + OFF_VH + off, &g_Vth[(size_t)tile * 4096 + r * 64 + c8]);
        cpasync16(kvb + OFF_VL + off, &g_Vtl[(size_t)tile * 4096 + r * 64 + c8]);
    }
    cp_commit();
}

__global__ __launch_bounds__(256) void attn_mma(float* __restrict__ Out)
{
    extern __shared__ char sm[];
    const uint32_t sb = smem_u32(sm);
    const int tid  = threadIdx.x;
    const int lane = tid & 31;
    const int wid  = tid >> 5;
    const int rg   = wid & 3;
    const int jc   = wid >> 2;
    const int b    = blockIdx.x >> 6;
    const int qt   = blockIdx.x & 63;
    const int n0   = b * LSEQ + qt * 64;

    int kt0 = qt - 5;
    if (kt0 < 0) kt0 = 0;
    const int kt1 = qt;

    // Q tiles (plain LDG/STS; covered by first sync)
#pragma unroll
    for (int it = 0; it < 2; it++) {
        int s = it * 256 + tid;
        int r = s >> 3, c8 = (s & 7) << 3;
        uint32_t off = (uint32_t)(r * AS + c8) * 2;
        *(uint4*)(sm + OQH_A + off) = *(const uint4*)&g_Qh[(size_t)(n0 + r) * DIM + c8];
        *(uint4*)(sm + OQL_A + off) = *(const uint4*)&g_Ql[(size_t)(n0 + r) * DIM + c8];
    }

    // prologue: prefetch kt0 tiles into buf0
    {
        const int m0 = b * LSEQ + kt0 * 64;
        attn_prefetch_kv(sb + OKV, m0, m0 >> 6, tid);
    }

    float oacc[8][4];
#pragma unroll
    for (int d = 0; d < 8; d++)
#pragma unroll
        for (int c = 0; c < 4; c++) oacc[d][c] = 0.f;

    const int r0 = rg * 16 + (lane >> 2);
    const float gi0 = exp2f((float)r0 * LOG2GAMMA);
    const float gi1 = exp2f((float)(r0 + 8) * LOG2GAMMA);
    float gj[4][2];
#pragma unroll
    for (int jt = 0; jt < 4; jt++) {
        int j = jc * 32 + jt * 8 + ((lane & 3) << 1);
        gj[jt][0] = exp2f(-(float)j * LOG2GAMMA);
        gj[jt][1] = exp2f(-(float)(j + 1) * LOG2GAMMA);
    }

    const int lrow = lane & 15;
    const int lcg  = (lane >> 4) << 3;

    for (int kt = kt0; kt <= kt1; kt++) {
        const uint32_t kvb = sb + OKV + (uint32_t)((kt - kt0) & 1) * KVBUF;
        cp_wait<0>();
        __syncthreads();
        if (kt < kt1) {
            const int m0n = b * LSEQ + (kt + 1) * 64;
            attn_prefetch_kv(sb + OKV + (uint32_t)((kt - kt0 + 1) & 1) * KVBUF,
                             m0n, m0n >> 6, tid);
        }

        // ---- S = Q K^T (3-term) ----
        float sfrag[4][4];
#pragma unroll
        for (int jt = 0; jt < 4; jt++)
#pragma unroll
            for (int c = 0; c < 4; c++) sfrag[jt][c] = 0.f;

#pragma unroll
        for (int ks = 0; ks < 4; ks++) {
            uint32_t aoff = (uint32_t)((rg * 16 + lrow) * AS + ks * 16 + lcg) * 2;
            uint32_t ah[4], al[4];
            ldsm4(ah, sb + OQH_A + aoff);
            ldsm4(al, sb + OQL_A + aoff);
            uint32_t bh[2][4], bl[2][4];
#pragma unroll
            for (int jg = 0; jg < 2; jg++) {
                uint32_t boff = (uint32_t)((jc * 32 + jg * 16 + lrow) * AS + ks * 16 + lcg) * 2;
                ldsm4(bh[jg], kvb + OFF_KH + boff);
                ldsm4(bl[jg], kvb + OFF_KL + boff);
            }
#pragma unroll
            for (int jt = 0; jt < 4; jt++) {
                int jg = jt >> 1, sel = jt & 1;
                uint32_t b0h = bh[jg][sel], b1h = bh[jg][sel + 2];
                uint32_t b0l = bl[jg][sel], b1l = bl[jg][sel + 2];
                mma_bf16(sfrag[jt], ah, b0h, b1h);
                mma_bf16(sfrag[jt], ah, b0l, b1l);
                mma_bf16(sfrag[jt], al, b0h, b1h);
            }
        }

        // ---- decay + mask + frag-direct hi/lo conversion ----
        const float basekt = exp2f((float)((qt - kt) * 64) * LOG2GAMMA);
        uint32_t shh[2][4], sll[2][4];
#pragma unroll
        for (int jt = 0; jt < 4; jt++) {
            float w0 = basekt * gj[jt][0];
            float w1 = basekt * gj[jt][1];
            float v0 = sfrag[jt][0] * gi0 * w0;
            float v1 = sfrag[jt][1] * gi0 * w1;
            float v2 = sfrag[jt][2] * gi1 * w0;
            float v3 = sfrag[jt][3] * gi1 * w1;
            if (kt == qt) {
                int j0 = jc * 32 + jt * 8 + ((lane & 3) << 1);
                if (r0 < j0)         v0 = 0.f;
                if (r0 < j0 + 1)     v1 = 0.f;
                if (r0 + 8 < j0)     v2 = 0.f;
                if (r0 + 8 < j0 + 1) v3 = 0.f;
            }
            __nv_bfloat16 h0 = __float2bfloat16(v0);
            __nv_bfloat16 h1 = __float2bfloat16(v1);
            __nv_bfloat16 h2 = __float2bfloat16(v2);
            __nv_bfloat16 h3 = __float2bfloat16(v3);
            int ks2 = jt >> 1, odd = jt & 1;
            shh[ks2][odd * 2 + 0] = pack2(h0, h1);
            shh[ks2][odd * 2 + 1] = pack2(h2, h3);
            sll[ks2][odd * 2 + 0] =
                pack2(__float2bfloat16(v0 - __bfloat162float(h0)),
                      __float2bfloat16(v1 - __bfloat162float(h1)));
            sll[ks2][odd * 2 + 1] =
                pack2(__float2bfloat16(v2 - __bfloat162float(h2)),
                      __float2bfloat16(v3 - __bfloat162float(h3)));
        }

        // ---- O += S V (3-term) ----
#pragma unroll
        for (int ks2 = 0; ks2 < 2; ks2++) {
            uint32_t vbh[4][4], vbl[4][4];
#pragma unroll
            for (int dg = 0; dg < 4; dg++) {
                uint32_t voff = (uint32_t)((dg * 16 + lrow) * AS + jc * 32 + ks2 * 16 + lcg) * 2;
                ldsm4(vbh[dg], kvb + OFF_VH + voff);
                ldsm4(vbl[dg], kvb + OFF_VL + voff);
            }
#pragma unroll
            for (int dt = 0; dt < 8; dt++) {
                int dg = dt >> 1, sel = dt & 1;
                uint32_t b0h = vbh[dg][sel], b1h = vbh[dg][sel + 2];
                uint32_t b0l = vbl[dg][sel], b1l = vbl[dg][sel + 2];
                mma_bf16(oacc[dt], shh[ks2], b0h, b1h);
                mma_bf16(oacc[dt], sll[ks2], b0h, b1h);
                mma_bf16(oacc[dt], shh[ks2], b0l, b1l);
            }
        }
    }

    // ---- pair reduction (jc) over smem, then store Out ----
    __syncthreads();
    float* red = (float*)sm;                 // reuses Q area
    const int c2 = (lane & 3) << 1;
    if (jc == 1) {
#pragma unroll
        for (int dt = 0; dt < 8; dt++) {
            int d = dt * 8 + c2;
            red[r0 * RED_S + d]           = oacc[dt][0];
            red[r0 * RED_S + d + 1]       = oacc[dt][1];
            red[(r0 + 8) * RED_S + d]     = oacc[dt][2];
            red[(r0 + 8) * RED_S + d + 1] = oacc[dt][3];
        }
    }
    __syncthreads();
    if (jc == 0) {
#pragma unroll
        for (int dt = 0; dt < 8; dt++) {
            int d = dt * 8 + c2;
            float2 lo = make_float2(oacc[dt][0] + red[r0 * RED_S + d],
                                    oacc[dt][1] + red[r0 * RED_S + d + 1]);
            float2 hi = make_float2(oacc[dt][2] + red[(r0 + 8) * RED_S + d],
                                    oacc[dt][3] + red[(r0 + 8) * RED_S + d + 1]);
            *(float2*)&Out[(size_t)(n0 + r0) * DIM + d]     = lo;
            *(float2*)&Out[(size_t)(n0 + r0 + 8) * DIM + d] = hi;
        }
    }
}

// ---------------------------------------------------------------------------
extern "C" void kernel_launch(void* const* d_in, const int* in_sizes, int n_in,
                              void* d_out, int out_size)
{
    const float* X  = (const float*)d_in[0];
    const float* Wq = (const float*)d_in[1];
    const float* Wk = (const float*)d_in[2];
    const float* Wv = (const float*)d_in[3];
    float* Out = (float*)d_out;

    cudaFuncSetAttribute(qkv_mma, cudaFuncAttributeMaxDynamicSharedMemorySize,
                         QKV_SMEM);
    cudaFuncSetAttribute(attn_mma, cudaFuncAttributeMaxDynamicSharedMemorySize,
                         ATTN_SMEM);

    prep_all<<<256, 256>>>(Wq, Wk, Wv);
    qkv_mma<<<NTOK / 64, 512, QKV_SMEM>>>(X);
    attn_mma<<<BATCH * (LSEQ / 64), 256, ATTN_SMEM>>>(Out);
}